// round 2
// baseline (speedup 1.0000x reference)
#include <cuda_runtime.h>
#include <cuda_bf16.h>
#include <cstdint>

// word2vec negative-sampling loss:
//   second_emb  [200000, 128] f32
//   context_emb [200000, 128] f32
//   v_i, v_j    [131072] i32
//   negsamples  [5, 131072] i32
// out: scalar f32 = -mean_b( logsig(vi.vj) + sum_k logsig(-vi.neg_k) )

#define EMBED 128
#define NUM_NEG 5
#define TPB 256
#define WARPS_PER_BLOCK (TPB / 32)
#define NBLOCKS 1184   // 8 per SM x 148

__device__ float g_partials[NBLOCKS];
__device__ unsigned int g_ticket = 0;

__device__ __forceinline__ float log_sigmoid(float x) {
    // logsig(x) = min(x,0) - log1p(exp(-|x|))
    return fminf(x, 0.0f) - log1pf(expf(-fabsf(x)));
}

__device__ __forceinline__ float dot4(float4 a, float4 b) {
    return fmaf(a.x, b.x, fmaf(a.y, b.y, fmaf(a.z, b.z, a.w * b.w)));
}

__global__ void __launch_bounds__(TPB)
w2v_loss_fused(const float* __restrict__ second_emb,
               const float* __restrict__ context_emb,
               const int* __restrict__ v_i,
               const int* __restrict__ v_j,
               const int* __restrict__ negs,
               int batch, float inv_batch,
               float* __restrict__ out)
{
    const int lane   = threadIdx.x & 31;
    const int wInBlk = threadIdx.x >> 5;
    const int gwarp  = blockIdx.x * WARPS_PER_BLOCK + wInBlk;
    const int nwarps = gridDim.x * WARPS_PER_BLOCK;

    float acc = 0.0f;   // only meaningful on lane 0

    for (int e = gwarp; e < batch; e += nwarps) {
        const int ivi = __ldg(&v_i[e]);
        const int ivj = __ldg(&v_j[e]);
        int ineg[NUM_NEG];
        #pragma unroll
        for (int k = 0; k < NUM_NEG; k++)
            ineg[k] = __ldg(&negs[(size_t)k * batch + e]);

        // vi row: low reuse -> stream (evict-first), don't pollute L2
        const float4* vi_row = reinterpret_cast<const float4*>(
            second_emb + (size_t)ivi * EMBED);
        float4 a = __ldcs(&vi_row[lane]);

        // context rows: ~4x reuse, table fits L2 -> normal cached loads.
        // Issue all 6 before consuming (MLP).
        float4 r[NUM_NEG + 1];
        const float4* vj_row = reinterpret_cast<const float4*>(
            context_emb + (size_t)ivj * EMBED);
        r[0] = __ldg(&vj_row[lane]);
        #pragma unroll
        for (int k = 0; k < NUM_NEG; k++) {
            const float4* nrow = reinterpret_cast<const float4*>(
                context_emb + (size_t)ineg[k] * EMBED);
            r[k + 1] = __ldg(&nrow[lane]);
        }

        float d[NUM_NEG + 1];
        #pragma unroll
        for (int j = 0; j < NUM_NEG + 1; j++)
            d[j] = dot4(a, r[j]);

        #pragma unroll
        for (int off = 16; off > 0; off >>= 1) {
            #pragma unroll
            for (int j = 0; j < NUM_NEG + 1; j++)
                d[j] += __shfl_xor_sync(0xFFFFFFFFu, d[j], off);
        }

        if (lane == 0) {
            float l = log_sigmoid(d[0]);
            #pragma unroll
            for (int k = 0; k < NUM_NEG; k++)
                l += log_sigmoid(-d[k + 1]);
            acc += l;
        }
    }

    // ---- block reduction (deterministic) ----
    __shared__ float ws[WARPS_PER_BLOCK];
    if (lane == 0)
        ws[wInBlk] = acc;
    __syncthreads();

    if (threadIdx.x < 32) {
        float s = (threadIdx.x < WARPS_PER_BLOCK) ? ws[threadIdx.x] : 0.0f;
        #pragma unroll
        for (int off = 16; off > 0; off >>= 1)
            s += __shfl_xor_sync(0xFFFFFFFFu, s, off);
        if (threadIdx.x == 0)
            g_partials[blockIdx.x] = s;
    }

    // ---- last block folds the partials (no second launch) ----
    __shared__ int isLast;
    if (threadIdx.x == 0) {
        __threadfence();
        unsigned int old = atomicAdd(&g_ticket, 1u);
        isLast = (old == gridDim.x - 1) ? 1 : 0;
        if (isLast)
            g_ticket = 0;   // reset for next graph replay
    }
    __syncthreads();

    if (isLast) {
        float s = 0.0f;
        for (int i = threadIdx.x; i < (int)gridDim.x; i += TPB)
            s += g_partials[i];           // fixed order per thread
        #pragma unroll
        for (int off = 16; off > 0; off >>= 1)
            s += __shfl_xor_sync(0xFFFFFFFFu, s, off);
        __shared__ float fs[WARPS_PER_BLOCK];
        if (lane == 0)
            fs[wInBlk] = s;
        __syncthreads();
        if (threadIdx.x < 32) {
            float t = (threadIdx.x < WARPS_PER_BLOCK) ? fs[threadIdx.x] : 0.0f;
            #pragma unroll
            for (int off = 16; off > 0; off >>= 1)
                t += __shfl_xor_sync(0xFFFFFFFFu, t, off);
            if (threadIdx.x == 0)
                out[0] = -t * inv_batch;
        }
    }
}

extern "C" void kernel_launch(void* const* d_in, const int* in_sizes, int n_in,
                              void* d_out, int out_size)
{
    const float* second_emb  = (const float*)d_in[0];
    const float* context_emb = (const float*)d_in[1];
    const int*   v_i         = (const int*)d_in[2];
    const int*   v_j         = (const int*)d_in[3];
    const int*   negs        = (const int*)d_in[4];

    const int batch = in_sizes[2];  // 131072

    w2v_loss_fused<<<NBLOCKS, TPB>>>(second_emb, context_emb,
                                     v_i, v_j, negs,
                                     batch, 1.0f / (float)batch,
                                     (float*)d_out);
}